// round 2
// baseline (speedup 1.0000x reference)
#include <cuda_runtime.h>
#include <cstdint>

// RVQECell simulator: N=19 qubits, B=32.
// Layout: flat index idx, bit (18-l) = lane l. Lane 18 (ancilla) = bit 0,
// never touched -> treat state as 2^18 float2 per batch element.
// e = idx>>1 : e bit (17-l) = lane l (l = 0..17).
//
// Pass 1: tile over e bits 11..0 (lanes 6..17); fixed: batch b + e bits 17..12
//         (lanes 0..5, physical value a). Both bitflips folded in: logical
//         inout value v = a ^ f[b]; data read & written at physical a.
//         Applies: input layer (12 neurons) + 3x(12 Ry + 12 neurons), all in smem.
// Pass 2: tile over e bits 17..12 and 5..0; fixed: b + e bits 11..6 (m6).
//         Applies the 6 output neurons in-place + accumulates probs.
//
// Neuron angle tables: 54 x 2^17 (cos,sin), precomputed each launch.

#define TBL_BITS 17
#define NTBL (1 << TBL_BITS)

__device__ float2 g_tbl[54 * (size_t)NTBL];   // ~56 MB, fits L2

// ---------------------------------------------------------------------------
// Table precompute: phi = pi/2 + th1.x + x^T triu(th2,1) x over 17 control bits
// (control i = lane order ascending, mapped to table bit 16-i). Then one
// q(t)=atan2(sin^2,cos^2) application (ORDER=2): cosA = c^2/h, sinA = s^2/h.
// ---------------------------------------------------------------------------
__global__ void __launch_bounds__(256) k_tables(
    const float* __restrict__ w_in1, const float* __restrict__ w_in2,
    const float* __restrict__ w_k1,  const float* __restrict__ w_k2,
    const float* __restrict__ w_out1,const float* __restrict__ w_out2)
{
    __shared__ float th1[17];
    __shared__ float th2[17 * 17];
    int nid = blockIdx.x >> 9;                       // 512 blocks / neuron
    int x   = ((blockIdx.x & 511) << 8) | threadIdx.x;
    const float *t1, *t2;
    if (nid < 12)      { t1 = w_in1  + nid * 17;        t2 = w_in2 + nid * 289; }
    else if (nid < 48) { t1 = w_k1   + (nid - 12) * 17; t2 = w_k2  + (nid - 12) * 289; }
    else               { t1 = w_out1 + (nid - 48) * 17; t2 = w_out2 + (nid - 48) * 289; }
    if (threadIdx.x < 17) th1[threadIdx.x] = t1[threadIdx.x];
    for (int i = threadIdx.x; i < 289; i += 256) th2[i] = t2[i];
    __syncthreads();

    float bb[17];
#pragma unroll
    for (int i = 0; i < 17; ++i) bb[i] = (float)((x >> (16 - i)) & 1);

    float phi = 1.57079632679489662f;                // pi/2 bias
#pragma unroll
    for (int i = 0; i < 17; ++i) {
        float ti = th1[i];
#pragma unroll
        for (int j = i + 1; j < 17; ++j) ti = fmaf(bb[j], th2[i * 17 + j], ti);
        phi = fmaf(bb[i], ti, phi);
    }
    float s, c;
    sincosf(phi, &s, &c);
    float s2 = s * s, c2 = c * c;
    float r = rsqrtf(fmaf(s2, s2, c2 * c2));         // hyp >= sqrt(0.5), safe
    g_tbl[((size_t)nid << TBL_BITS) + x] = make_float2(c2 * r, s2 * r);
}

// ---------------------------------------------------------------------------
// Pair enumeration: q in [0, 2^11), insert 0 at bit ob -> p0; p1 = p0 | 1<<ob.
// For pass-1 neurons, removing bit ob from p0 (lane-ordered) gives exactly q,
// so the per-block table slice is tbl[(v<<11) + q] -> stage it in smem.
// ---------------------------------------------------------------------------
__device__ __forceinline__ void rot_pairs(float2* st, int ob, float cn, float sn)
{
    int tid = threadIdx.x;
    int msk = (1 << ob) - 1;
#pragma unroll
    for (int k = 0; k < 8; ++k) {
        int q  = tid + (k << 8);
        int lo = q & msk;
        int p0 = ((q ^ lo) << 1) | lo;
        int p1 = p0 | (1 << ob);
        float2 x0 = st[p0], x1 = st[p1];
        st[p0] = make_float2(fmaf(cn, x0.x, -sn * x1.x), fmaf(cn, x0.y, -sn * x1.y));
        st[p1] = make_float2(fmaf(sn, x0.x,  cn * x1.x), fmaf(sn, x0.y,  cn * x1.y));
    }
}

__device__ __forceinline__ void neuron_pairs(float2* st, const float2* tsh, int ob)
{
    int tid = threadIdx.x;
    int msk = (1 << ob) - 1;
#pragma unroll
    for (int k = 0; k < 8; ++k) {
        int q  = tid + (k << 8);
        int lo = q & msk;
        int p0 = ((q ^ lo) << 1) | lo;
        int p1 = p0 | (1 << ob);
        float2 cs = tsh[q];
        float2 x0 = st[p0], x1 = st[p1];
        st[p0] = make_float2(fmaf(cs.x, x0.x, -cs.y * x1.x), fmaf(cs.x, x0.y, -cs.y * x1.y));
        st[p1] = make_float2(fmaf(cs.y, x0.x,  cs.x * x1.x), fmaf(cs.y, x0.y,  cs.x * x1.y));
    }
}

__global__ void __launch_bounds__(256) k_pass1(
    const float2* __restrict__ gin, const int* __restrict__ inputs,
    const float* __restrict__ w_u, float2* __restrict__ gout)
{
    __shared__ float2 st[4096];     // 32 KB state tile (lanes 6..17)
    __shared__ float2 tsh[2048];    // 16 KB staged angle-table slice
    int tid = threadIdx.x;
    int b = blockIdx.x >> 6;
    int a = blockIdx.x & 63;        // physical inout bits (e bits 17..12)
    int f = 0;
#pragma unroll
    for (int i = 0; i < 6; ++i) f |= inputs[b * 6 + i] << (5 - i);
    int v = a ^ f;                  // logical inout value after bitflip

    const float2* src = gin  + ((size_t)b << 18) + ((size_t)a << 12);
    float2*       dst = gout + ((size_t)b << 18) + ((size_t)a << 12);

#pragma unroll
    for (int k = 0; k < 16; ++k) st[tid + (k << 8)] = src[tid + (k << 8)];

    for (int grp = 0; grp < 4; ++grp) {            // input layer + 3 stages
        if (grp > 0) {
            int stg = grp - 1;
            for (int j = 0; j < 12; ++j) {
                float sn, cn;
                sincosf(w_u[stg * 12 + j], &sn, &cn);
                __syncthreads();
                rot_pairs(st, 11 - j, cn, sn);
            }
        }
        int nb = (grp == 0) ? 0 : 12 + (grp - 1) * 12;
        for (int j = 0; j < 12; ++j) {
            const float2* tb = g_tbl + ((size_t)(nb + j) << TBL_BITS) + ((size_t)v << 11);
            __syncthreads();                       // prior pass done (st & tsh)
#pragma unroll
            for (int k = 0; k < 8; ++k) tsh[tid + (k << 8)] = tb[tid + (k << 8)];
            __syncthreads();
            neuron_pairs(st, tsh, 11 - j);
        }
    }
    __syncthreads();
#pragma unroll
    for (int k = 0; k < 16; ++k) dst[tid + (k << 8)] = st[tid + (k << 8)];
}

__global__ void __launch_bounds__(256) k_pass2(
    float2* __restrict__ psi, float* __restrict__ probs)
{
    __shared__ float2 st[4096];
    int tid = threadIdx.x;
    int b  = blockIdx.x >> 6;
    int m6 = blockIdx.x & 63;       // lanes 6..11 (e bits 11..6), fixed
    int mb = m6 << 6;
    float2* base = psi + ((size_t)b << 18);

    // tile index t: bits 11..6 = e bits 17..12 (lanes 0..5), bits 5..0 = e bits 5..0
#pragma unroll
    for (int k = 0; k < 16; ++k) {
        int t = tid + (k << 8);
        st[t] = base[((size_t)(t >> 6) << 12) | mb | (t & 63)];
    }

    for (int j = 0; j < 6; ++j) {   // output neurons, lane j, tile bit 11-j
        int ob = 11 - j;
        const float2* tb = g_tbl + ((size_t)(48 + j) << TBL_BITS);
        int msk = (1 << ob) - 1;
        __syncthreads();
#pragma unroll
        for (int k = 0; k < 8; ++k) {
            int q  = tid + (k << 8);
            int lo = q & msk;
            int p0 = ((q ^ lo) << 1) | lo;
            int p1 = p0 | (1 << ob);
            // table idx: lanes 0..5\j (q bits 10..6) | lanes 6..11 (m6) | lanes 12..17 (q bits 5..0)
            float2 cs = __ldg(&tb[((q >> 6) << 12) | (m6 << 6) | (q & 63)]);
            float2 x0 = st[p0], x1 = st[p1];
            st[p0] = make_float2(fmaf(cs.x, x0.x, -cs.y * x1.x), fmaf(cs.x, x0.y, -cs.y * x1.y));
            st[p1] = make_float2(fmaf(cs.y, x0.x,  cs.x * x1.x), fmaf(cs.y, x0.y,  cs.x * x1.y));
        }
    }
    __syncthreads();

    float* pr = probs + b * 64;
#pragma unroll
    for (int k = 0; k < 16; ++k) {
        int t = tid + (k << 8);
        float2 x = st[t];
        base[((size_t)(t >> 6) << 12) | mb | (t & 63)] = x;
        float sq = fmaf(x.x, x.x, x.y * x.y);
#pragma unroll
        for (int o = 16; o > 0; o >>= 1) sq += __shfl_xor_sync(0xffffffffu, sq, o);
        if ((tid & 31) == 0) atomicAdd(pr + (t >> 6), sq);   // t>>6 warp-uniform
    }
}

// ---------------------------------------------------------------------------
extern "C" void kernel_launch(void* const* d_in, const int* in_sizes, int n_in,
                              void* d_out, int out_size)
{
    (void)in_sizes; (void)n_in; (void)out_size;
    const float* batch  = (const float*)d_in[0];
    const float* w_in1  = (const float*)d_in[1];
    const float* w_in2  = (const float*)d_in[2];
    const float* w_u    = (const float*)d_in[3];
    const float* w_k1   = (const float*)d_in[4];
    const float* w_k2   = (const float*)d_in[5];
    const float* w_out1 = (const float*)d_in[6];
    const float* w_out2 = (const float*)d_in[7];
    const int*   inputs = (const int*)d_in[8];

    float*  probs = (float*)d_out;                 // [32, 64]
    float2* psi   = (float2*)(probs + 32 * 64);    // [32, 2^18] float2 (= [32, 2^19] f32)

    cudaMemsetAsync(probs, 0, 32 * 64 * sizeof(float));
    k_tables<<<54 * 512, 256>>>(w_in1, w_in2, w_k1, w_k2, w_out1, w_out2);
    k_pass1 <<<32 * 64, 256>>>((const float2*)batch, inputs, w_u, psi);
    k_pass2 <<<32 * 64, 256>>>(psi, probs);
}

// round 3
// speedup vs baseline: 1.5585x; 1.5585x over previous
#include <cuda_runtime.h>
#include <cstdint>

// RVQECell, N=19 qubits, B=32. Lane 18 untouched -> state = 2^18 float2/batch.
// e-index: bit (17-l) = lane l.
// Pass1: tile = e[11:0] (lanes 6..17), fixed (b, a=e[17:12]); logical v=a^f.
//   Register-tiled: 256 thr x 16 float2 regs; 15 shared round-trips cover
//   input layer (12 neurons) + 3 x (12 Ry + 12 neurons) = 84 gates.
// Pass2: tile bits = e[17:12] ++ e[5:0], fixed (b, m6=e[11:6]); 2 rounds for
//   the 6 output neurons + probs marginal.
// Tables: 54 x 2^17 (cosA, sinA).

typedef unsigned long long u64;

#define TBL_BITS 17
__device__ float2 g_tbl[54 * (size_t)(1 << TBL_BITS)];   // ~56 MB

// ---------------- packed f32x2 helpers ----------------
__device__ __forceinline__ u64 mul2(u64 a, u64 b){ u64 d; asm("mul.rn.f32x2 %0,%1,%2;":"=l"(d):"l"(a),"l"(b)); return d; }
__device__ __forceinline__ u64 fma2(u64 a, u64 b, u64 c){ u64 d; asm("fma.rn.f32x2 %0,%1,%2,%3;":"=l"(d):"l"(a),"l"(b),"l"(c)); return d; }
__device__ __forceinline__ u64 bc2(float v){ u64 d; asm("mov.b64 %0,{%1,%1};":"=l"(d):"f"(v)); return d; }

__device__ __forceinline__ void gapply(u64 &a, u64 &b, float c, float s){
    u64 cc = bc2(c), ss = bc2(s), ns = bc2(-s);
    u64 t0 = mul2(ns, b);
    u64 t1 = mul2(cc, b);
    u64 na = fma2(cc, a, t0);
    b = fma2(ss, a, t1);
    a = na;
}

// shared-index swizzle: bank-conflict-free for all three access patterns
__device__ __forceinline__ int sw(int i){ return i ^ (((i>>4) ^ (i>>8)) & 0xF); }

// tile index for register set S (0: bits 11..8 in regs, 1: 7..4, 2: 3..0)
template<int S> __device__ __forceinline__ int tix(int tid, int m){
    return (S==0) ? ((m<<8)|tid)
         : (S==1) ? (((tid>>4)<<8)|(m<<4)|(tid&15))
                  : ((tid<<4)|m);
}
template<int S> __device__ __forceinline__ void ldr(u64* x, const u64* st, int tid){
#pragma unroll
    for(int m=0;m<16;++m) x[m] = st[sw(tix<S>(tid,m))];
}
template<int S> __device__ __forceinline__ void str(const u64* x, u64* st, int tid){
#pragma unroll
    for(int m=0;m<16;++m) st[sw(tix<S>(tid,m))] = x[m];
}

// apply neuron gate on register bit K; cs[mo] indexed by compressed other bits
template<int K> __device__ __forceinline__ void apply_neuron(u64* x, const float2* cs){
#pragma unroll
    for(int m=0;m<16;++m) if(!(m & (1<<K))){
        int mo = ((m >> (K+1)) << K) | (m & ((1<<K)-1));
        gapply(x[m], x[m | (1<<K)], cs[mo].x, cs[mo].y);
    }
}
template<int K> __device__ __forceinline__ void apply_ry(u64* x, float c, float s){
    u64 cc = bc2(c), ss = bc2(s), ns = bc2(-s);
#pragma unroll
    for(int m=0;m<16;++m) if(!(m & (1<<K))){
        u64 &a = x[m], &b = x[m | (1<<K)];
        u64 t0 = mul2(ns, b), t1 = mul2(cc, b);
        u64 na = fma2(cc, a, t0);
        b = fma2(ss, a, t1); a = na;
    }
}

// pass1 table-slice loads (q = tile index with gate bit removed; base has v<<11)
__device__ __forceinline__ void ldcs_H(float2* cs, const float2* tb, int tid){
#pragma unroll
    for(int mo=0;mo<8;++mo) cs[mo] = __ldg(tb + (mo<<8) + tid);
}
__device__ __forceinline__ void ldcs_M(float2* cs, const float2* tb, int tid){
    int hi = tid>>4, lo = tid&15;
#pragma unroll
    for(int mo=0;mo<8;++mo) cs[mo] = __ldg(tb + (hi<<7) + (mo<<4) + lo);
}
// L-round gather is stride-8 per thread -> stage slice through shared (swizzled)
__device__ __forceinline__ void stage_L(float2* tsh, const float2* tb, int tid){
#pragma unroll
    for(int k=0;k<8;++k){ int j = tid + (k<<8); tsh[sw(j)] = __ldg(tb + j); }
}
__device__ __forceinline__ void ldcs_Lsh(float2* cs, const float2* tsh, int tid){
#pragma unroll
    for(int mo=0;mo<8;++mo) cs[mo] = tsh[sw((tid<<3)|mo)];
}

// ---------------------------------------------------------------------------
// k_tables: phi = pi/2 + th1.x + x^T triu(th2,1) x, factored:
//   hi 9 bits (block-constant K), 8 linear coeffs cf[j], low-low quadratic.
// alpha = q(phi): cosA = cos^2/h, sinA = sin^2/h, h = sqrt(s^4+c^4).
// ---------------------------------------------------------------------------
__global__ void __launch_bounds__(256) k_tables(
    const float* __restrict__ w_in1, const float* __restrict__ w_in2,
    const float* __restrict__ w_k1,  const float* __restrict__ w_k2,
    const float* __restrict__ w_out1,const float* __restrict__ w_out2)
{
    __shared__ float th1[17];
    __shared__ float th2[289];
    __shared__ float cf[8];
    __shared__ float Ksh;
    int tid = threadIdx.x;
    int nid = blockIdx.x >> 9;
    int hi9 = blockIdx.x & 511;
    const float *t1, *t2;
    if (nid < 12)      { t1 = w_in1  + nid*17;      t2 = w_in2 + nid*289; }
    else if (nid < 48) { t1 = w_k1   + (nid-12)*17; t2 = w_k2  + (nid-12)*289; }
    else               { t1 = w_out1 + (nid-48)*17; t2 = w_out2 + (nid-48)*289; }
    if (tid < 17) th1[tid] = t1[tid];
    for (int i = tid; i < 289; i += 256) th2[i] = t2[i];
    __syncthreads();

    float bh[9];
#pragma unroll
    for(int i=0;i<9;++i) bh[i] = (float)((hi9 >> (8-i)) & 1);
    if (tid < 8){
        float c = th1[9+tid];
#pragma unroll
        for(int i=0;i<9;++i) c = fmaf(bh[i], th2[i*17 + 9 + tid], c);
        cf[tid] = c;
    } else if (tid == 8){
        float K = 1.57079632679489662f;
#pragma unroll
        for(int i=0;i<9;++i){
            float ti = th1[i];
#pragma unroll
            for(int j=i+1;j<9;++j) ti = fmaf(bh[j], th2[i*17+j], ti);
            K = fmaf(bh[i], ti, K);
        }
        Ksh = K;
    }
    __syncthreads();

    float bl[8];
#pragma unroll
    for(int j=0;j<8;++j) bl[j] = (float)((tid >> (7-j)) & 1);
    float phi = Ksh;
#pragma unroll
    for(int j=0;j<8;++j){
        float tj = cf[j];
#pragma unroll
        for(int j2=j+1;j2<8;++j2) tj = fmaf(bl[j2], th2[(9+j)*17 + 9+j2], tj);
        phi = fmaf(bl[j], tj, phi);
    }
    float s, c;
    sincosf(phi, &s, &c);
    float s2 = s*s, c2 = c*c;
    float r = rsqrtf(fmaf(s2, s2, c2*c2));
    g_tbl[((size_t)nid << TBL_BITS) | (hi9 << 8) | tid] = make_float2(c2*r, s2*r);
}

// ---------------------------------------------------------------------------
__global__ void __launch_bounds__(256) k_pass1(
    const u64* __restrict__ gin, const int* __restrict__ inputs,
    const float* __restrict__ w_u, u64* __restrict__ gout)
{
    __shared__ u64 st[4096];        // 32 KB state tile
    __shared__ float2 tsh[2048];    // 16 KB table staging (L rounds)
    int tid = threadIdx.x;
    int b = blockIdx.x >> 6;
    int a = blockIdx.x & 63;
    int f = 0;
#pragma unroll
    for(int i=0;i<6;++i) f |= inputs[b*6+i] << (5-i);
    int v = a ^ f;

    const u64* src = gin  + ((size_t)b<<18) + ((size_t)a<<12);
    u64*       dst = gout + ((size_t)b<<18) + ((size_t)a<<12);

    u64 x[16];
    float2 cs[8];

#define NG_H(nid, K) { ldcs_H(cs, g_tbl + (((size_t)(nid))<<TBL_BITS) + ((size_t)v<<11), tid); apply_neuron<K>(x, cs); }
#define NG_M(nid, K) { ldcs_M(cs, g_tbl + (((size_t)(nid))<<TBL_BITS) + ((size_t)v<<11), tid); apply_neuron<K>(x, cs); }
#define NG_L(nid, K) { __syncthreads(); stage_L(tsh, g_tbl + (((size_t)(nid))<<TBL_BITS) + ((size_t)v<<11), tid); __syncthreads(); ldcs_Lsh(cs, tsh, tid); apply_neuron<K>(x, cs); }
#define RY4(stg, j0) { float sn, cn; \
    sincosf(w_u[(stg)*12 + (j0)+0], &sn, &cn); apply_ry<3>(x, cn, sn); \
    sincosf(w_u[(stg)*12 + (j0)+1], &sn, &cn); apply_ry<2>(x, cn, sn); \
    sincosf(w_u[(stg)*12 + (j0)+2], &sn, &cn); apply_ry<1>(x, cn, sn); \
    sincosf(w_u[(stg)*12 + (j0)+3], &sn, &cn); apply_ry<0>(x, cn, sn); }

    // R1: input neurons lanes 6..9 (bits 11..8), load straight from global
#pragma unroll
    for(int m=0;m<16;++m) x[m] = src[(m<<8)|tid];
    NG_H(0,3) NG_H(1,2) NG_H(2,1) NG_H(3,0)
    str<0>(x, st, tid); __syncthreads();
    // R2
    ldr<1>(x, st, tid);
    NG_M(4,3) NG_M(5,2) NG_M(6,1) NG_M(7,0)
    str<1>(x, st, tid); __syncthreads();
    // R3: input neurons bits 3..0, then Ry(st0) lanes 14..17
    ldr<2>(x, st, tid);
    NG_L(8,3) NG_L(9,2) NG_L(10,1) NG_L(11,0)
    RY4(0, 8)
    str<2>(x, st, tid); __syncthreads();
    // R4
    ldr<1>(x, st, tid); RY4(0, 4); str<1>(x, st, tid); __syncthreads();
    // R5: Ry(st0) lanes 6..9 then neurons st0 bits 11..8
    ldr<0>(x, st, tid); RY4(0, 0);
    NG_H(12,3) NG_H(13,2) NG_H(14,1) NG_H(15,0)
    str<0>(x, st, tid); __syncthreads();
    // R6
    ldr<1>(x, st, tid);
    NG_M(16,3) NG_M(17,2) NG_M(18,1) NG_M(19,0)
    str<1>(x, st, tid); __syncthreads();
    // R7
    ldr<2>(x, st, tid);
    NG_L(20,3) NG_L(21,2) NG_L(22,1) NG_L(23,0)
    RY4(1, 8)
    str<2>(x, st, tid); __syncthreads();
    // R8
    ldr<1>(x, st, tid); RY4(1, 4); str<1>(x, st, tid); __syncthreads();
    // R9
    ldr<0>(x, st, tid); RY4(1, 0);
    NG_H(24,3) NG_H(25,2) NG_H(26,1) NG_H(27,0)
    str<0>(x, st, tid); __syncthreads();
    // R10
    ldr<1>(x, st, tid);
    NG_M(28,3) NG_M(29,2) NG_M(30,1) NG_M(31,0)
    str<1>(x, st, tid); __syncthreads();
    // R11
    ldr<2>(x, st, tid);
    NG_L(32,3) NG_L(33,2) NG_L(34,1) NG_L(35,0)
    RY4(2, 8)
    str<2>(x, st, tid); __syncthreads();
    // R12
    ldr<1>(x, st, tid); RY4(2, 4); str<1>(x, st, tid); __syncthreads();
    // R13
    ldr<0>(x, st, tid); RY4(2, 0);
    NG_H(36,3) NG_H(37,2) NG_H(38,1) NG_H(39,0)
    str<0>(x, st, tid); __syncthreads();
    // R14
    ldr<1>(x, st, tid);
    NG_M(40,3) NG_M(41,2) NG_M(42,1) NG_M(43,0)
    str<1>(x, st, tid); __syncthreads();
    // R15: neurons st2 bits 3..0; bounce through shared for coalesced store
    ldr<2>(x, st, tid);
    NG_L(44,3) NG_L(45,2) NG_L(46,1) NG_L(47,0)
    str<2>(x, st, tid); __syncthreads();
#pragma unroll
    for(int k=0;k<16;++k){ int t = tid + (k<<8); dst[t] = st[sw(t)]; }

#undef NG_H
#undef NG_M
#undef NG_L
#undef RY4
}

// ---------------------------------------------------------------------------
__global__ void __launch_bounds__(256) k_pass2(
    u64* __restrict__ psi, float* __restrict__ probs)
{
    __shared__ u64 st[4096];
    __shared__ float sp[64];
    int tid = threadIdx.x;
    int b  = blockIdx.x >> 6;
    int m6 = blockIdx.x & 63;
    u64* base = psi + ((size_t)b<<18);
    if (tid < 64) sp[tid] = 0.0f;

    u64 x[16];
    float2 cs[8];

    // R1: H set (tile bits 11..8 in regs); tile t[11:6]=lanes0..5, t[5:0]=lanes12..17
    int t76 = tid >> 6, lo6 = tid & 63;
#pragma unroll
    for(int m=0;m<16;++m){
        int t = (m<<8)|tid;
        x[m] = base[((size_t)(t>>6)<<12) | (m6<<6) | (t&63)];
    }
#define NG2_H(j, K) { const float2* tb = g_tbl + ((size_t)(48+(j))<<TBL_BITS); \
    _Pragma("unroll") for(int mo=0;mo<8;++mo) \
        cs[mo] = __ldg(tb + (((mo<<2)|t76)<<12) + (m6<<6) + lo6); \
    apply_neuron<K>(x, cs); }
    NG2_H(0,3) NG2_H(1,2) NG2_H(2,1) NG2_H(3,0)
#undef NG2_H
    str<0>(x, st, tid); __syncthreads();

    // R2: M set (tile bits 7..4 in regs); neurons j=4 (bit7,K=3), j=5 (bit6,K=2)
    ldr<1>(x, st, tid);
    int hi = tid>>4, lo = tid&15;
    {
        const float2* tb = g_tbl + ((size_t)52<<TBL_BITS);
#pragma unroll
        for(int mo=0;mo<8;++mo)
            cs[mo] = __ldg(tb + ((((hi<<1)|(mo>>2))<<12) + (m6<<6) + ((mo&3)<<4) + lo));
        apply_neuron<3>(x, cs);
    }
    {
        const float2* tb = g_tbl + ((size_t)53<<TBL_BITS);
#pragma unroll
        for(int mo=0;mo<8;++mo)
            cs[mo] = __ldg(tb + ((((hi<<1)|(mo>>2))<<12) + (m6<<6) + ((mo&3)<<4) + lo));
        apply_neuron<2>(x, cs);
    }
    // store to global + probs marginal (prob index p = t[11:6] = (hi<<2)|(m>>2))
    float part[4] = {0.f, 0.f, 0.f, 0.f};
#pragma unroll
    for(int m=0;m<16;++m){
        int t = (hi<<8)|(m<<4)|lo;
        base[((size_t)(t>>6)<<12) | (m6<<6) | (t&63)] = x[m];
        float xl, xh;
        asm("mov.b64 {%0,%1},%2;" : "=f"(xl), "=f"(xh) : "l"(x[m]));
        part[m>>2] += fmaf(xl, xl, xh*xh);
    }
#pragma unroll
    for(int g=0; g<4; ++g) atomicAdd(&sp[(hi<<2)|g], part[g]);
    __syncthreads();
    if (tid < 64) atomicAdd(&probs[b*64 + tid], sp[tid]);
}

// ---------------------------------------------------------------------------
extern "C" void kernel_launch(void* const* d_in, const int* in_sizes, int n_in,
                              void* d_out, int out_size)
{
    (void)in_sizes; (void)n_in; (void)out_size;
    const float* w_in1  = (const float*)d_in[1];
    const float* w_in2  = (const float*)d_in[2];
    const float* w_u    = (const float*)d_in[3];
    const float* w_k1   = (const float*)d_in[4];
    const float* w_k2   = (const float*)d_in[5];
    const float* w_out1 = (const float*)d_in[6];
    const float* w_out2 = (const float*)d_in[7];
    const int*   inputs = (const int*)d_in[8];

    float* probs = (float*)d_out;                 // [32, 64]
    u64*   psi   = (u64*)(probs + 32 * 64);       // [32, 2^18] float2

    cudaMemsetAsync(probs, 0, 32 * 64 * sizeof(float));
    k_tables<<<54 * 512, 256>>>(w_in1, w_in2, w_k1, w_k2, w_out1, w_out2);
    k_pass1 <<<32 * 64, 256>>>((const u64*)d_in[0], inputs, w_u, psi);
    k_pass2 <<<32 * 64, 256>>>(psi, probs);
}

// round 4
// speedup vs baseline: 2.0891x; 1.3405x over previous
#include <cuda_runtime.h>
#include <cstdint>

// RVQECell, N=19 qubits, B=32. Lane 18 untouched -> state = 2^18 float2/batch.
// e-index: bit (17-l) = lane l.
// Pass1: tile = e[11:0] (lanes 6..17), fixed (b, a=e[17:12]); logical v=a^f.
//   Register-tiled: 256 thr x 16 float2; 15 shared round-trips cover
//   input layer (12 neurons) + 3 x (12 Ry + 12 neurons) = 84 gates.
//   Table cs loads double-buffered straight from L2 (no smem staging).
// Pass2: tile bits = e[17:12] ++ e[5:0], fixed (b, m6=e[11:6]); 6 output
//   neurons + probs marginal.
// Tables: 54 x 2^17 (cosA, sinA), 2 entries per thread in k_tables.

typedef unsigned long long u64;

#define TBL_BITS 17
__device__ float2 g_tbl[54 * (size_t)(1 << TBL_BITS)];   // ~56 MB

// ---------------- packed f32x2 helpers ----------------
__device__ __forceinline__ u64 mul2(u64 a, u64 b){ u64 d; asm("mul.rn.f32x2 %0,%1,%2;":"=l"(d):"l"(a),"l"(b)); return d; }
__device__ __forceinline__ u64 fma2(u64 a, u64 b, u64 c){ u64 d; asm("fma.rn.f32x2 %0,%1,%2,%3;":"=l"(d):"l"(a),"l"(b),"l"(c)); return d; }
__device__ __forceinline__ u64 bc2(float v){ u64 d; asm("mov.b64 %0,{%1,%1};":"=l"(d):"f"(v)); return d; }

__device__ __forceinline__ void gapply(u64 &a, u64 &b, float c, float s){
    u64 cc = bc2(c), ss = bc2(s), ns = bc2(-s);
    u64 t0 = mul2(ns, b);
    u64 t1 = mul2(cc, b);
    u64 na = fma2(cc, a, t0);
    b = fma2(ss, a, t1);
    a = na;
}

// shared-index swizzle: bank-conflict-free for all three access patterns
__device__ __forceinline__ int sw(int i){ return i ^ (((i>>4) ^ (i>>8)) & 0xF); }

// tile index for register set S (0: bits 11..8 in regs, 1: 7..4, 2: 3..0)
template<int S> __device__ __forceinline__ int tix(int tid, int m){
    return (S==0) ? ((m<<8)|tid)
         : (S==1) ? (((tid>>4)<<8)|(m<<4)|(tid&15))
                  : ((tid<<4)|m);
}
template<int S> __device__ __forceinline__ void ldr(u64* x, const u64* st, int tid){
#pragma unroll
    for(int m=0;m<16;++m) x[m] = st[sw(tix<S>(tid,m))];
}
template<int S> __device__ __forceinline__ void str(const u64* x, u64* st, int tid){
#pragma unroll
    for(int m=0;m<16;++m) st[sw(tix<S>(tid,m))] = x[m];
}

// apply neuron gate on register bit K; cs[mo] indexed by compressed other bits
template<int K> __device__ __forceinline__ void apply_neuron(u64* x, const float2* cs){
#pragma unroll
    for(int m=0;m<16;++m) if(!(m & (1<<K))){
        int mo = ((m >> (K+1)) << K) | (m & ((1<<K)-1));
        gapply(x[m], x[m | (1<<K)], cs[mo].x, cs[mo].y);
    }
}
template<int K> __device__ __forceinline__ void apply_ry(u64* x, float c, float s){
    u64 cc = bc2(c), ss = bc2(s), ns = bc2(-s);
#pragma unroll
    for(int m=0;m<16;++m) if(!(m & (1<<K))){
        u64 &a = x[m], &b = x[m | (1<<K)];
        u64 t0 = mul2(ns, b), t1 = mul2(cc, b);
        u64 na = fma2(cc, a, t0);
        b = fma2(ss, a, t1); a = na;
    }
}

// pass1 table-slice loads (q = tile index with gate bit removed; base has v<<11)
__device__ __forceinline__ void ldcs_H(float2* cs, const float2* tb, int tid){
#pragma unroll
    for(int mo=0;mo<8;++mo) cs[mo] = __ldg(tb + (mo<<8) + tid);
}
__device__ __forceinline__ void ldcs_M(float2* cs, const float2* tb, int tid){
    int hi = tid>>4, lo = tid&15;
#pragma unroll
    for(int mo=0;mo<8;++mo) cs[mo] = __ldg(tb + (hi<<7) + (mo<<4) + lo);
}
// L set: q = (tid<<3)|mo -> 8 consecutive float2 = 4x float4, fully coalesced
__device__ __forceinline__ void ldcs_L(float2* cs, const float2* tb, int tid){
    const float4* t4 = reinterpret_cast<const float4*>(tb + (tid<<3));
#pragma unroll
    for(int i=0;i<4;++i){
        float4 w = __ldg(t4 + i);
        cs[2*i]   = make_float2(w.x, w.y);
        cs[2*i+1] = make_float2(w.z, w.w);
    }
}

// ---------------------------------------------------------------------------
// k_tables: phi = pi/2 + th1.x + x^T triu(th2,1) x over 17 control bits.
// Factored: hi 8 bits (block) -> constant K + 9 linear coeffs cf[j];
// thread does 8 mid bits (36 FMA quadratic) and both values of the last bit
// (delta = cf[8] + 8 FMAs). alpha = q(phi): cosA=c^2/h, sinA=s^2/h.
// ---------------------------------------------------------------------------
__global__ void __launch_bounds__(256) k_tables(
    const float* __restrict__ w_in1, const float* __restrict__ w_in2,
    const float* __restrict__ w_k1,  const float* __restrict__ w_k2,
    const float* __restrict__ w_out1,const float* __restrict__ w_out2)
{
    __shared__ float th2[289];
    __shared__ float cf[9];
    __shared__ float Ksh;
    int tid = threadIdx.x;
    int nid = blockIdx.x >> 8;
    int hi8 = blockIdx.x & 255;                    // controls 0..7
    const float *t1, *t2;
    if (nid < 12)      { t1 = w_in1  + nid*17;      t2 = w_in2 + nid*289; }
    else if (nid < 48) { t1 = w_k1   + (nid-12)*17; t2 = w_k2  + (nid-12)*289; }
    else               { t1 = w_out1 + (nid-48)*17; t2 = w_out2 + (nid-48)*289; }
    for (int i = tid; i < 289; i += 256) th2[i] = t2[i];
    __syncthreads();

    float bh[8];
#pragma unroll
    for(int i=0;i<8;++i) bh[i] = (float)((hi8 >> (7-i)) & 1);
    if (tid < 9){
        float c = t1[8+tid];
#pragma unroll
        for(int i=0;i<8;++i) c = fmaf(bh[i], th2[i*17 + 8 + tid], c);
        cf[tid] = c;
    } else if (tid == 9){
        float K = 1.57079632679489662f;
#pragma unroll
        for(int i=0;i<8;++i){
            float ti = t1[i];
#pragma unroll
            for(int j=i+1;j<8;++j) ti = fmaf(bh[j], th2[i*17+j], ti);
            K = fmaf(bh[i], ti, K);
        }
        Ksh = K;
    }
    __syncthreads();

    float bl[8];                                   // controls 8..15 (tid bits)
#pragma unroll
    for(int j=0;j<8;++j) bl[j] = (float)((tid >> (7-j)) & 1);
    float phi0 = Ksh;
#pragma unroll
    for(int j=0;j<8;++j){
        float tj = cf[j];
#pragma unroll
        for(int j2=j+1;j2<8;++j2) tj = fmaf(bl[j2], th2[(8+j)*17 + 8+j2], tj);
        phi0 = fmaf(bl[j], tj, phi0);
    }
    float dl = cf[8];                              // control 16 (last bit) delta
#pragma unroll
    for(int j=0;j<8;++j) dl = fmaf(bl[j], th2[(8+j)*17 + 16], dl);
    float phi1 = phi0 + dl;

    float s0, c0, s1, c1;
    sincosf(phi0, &s0, &c0);
    sincosf(phi1, &s1, &c1);
    float s20 = s0*s0, c20 = c0*c0, r0 = rsqrtf(fmaf(s20,s20,c20*c20));
    float s21 = s1*s1, c21 = c1*c1, r1 = rsqrtf(fmaf(s21,s21,c21*c21));
    float4* out4 = reinterpret_cast<float4*>(g_tbl);
    out4[(((size_t)nid << TBL_BITS) | ((size_t)hi8 << 9) | (tid << 1)) >> 1]
        = make_float4(c20*r0, s20*r0, c21*r1, s21*r1);
}

// ---------------------------------------------------------------------------
__global__ void __launch_bounds__(256, 3) k_pass1(
    const u64* __restrict__ gin, const int* __restrict__ inputs,
    const float* __restrict__ w_u, u64* __restrict__ gout)
{
    __shared__ u64 st[4096];        // 32 KB state tile
    int tid = threadIdx.x;
    int b = blockIdx.x >> 6;
    int a = blockIdx.x & 63;
    int f = 0;
#pragma unroll
    for(int i=0;i<6;++i) f |= inputs[b*6+i] << (5-i);
    int v = a ^ f;

    const u64* src = gin  + ((size_t)b<<18) + ((size_t)a<<12);
    u64*       dst = gout + ((size_t)b<<18) + ((size_t)a<<12);

    u64 x[16];
    float2 csa[8], csb[8];

#define TB(n) (g_tbl + (((size_t)(n))<<TBL_BITS) + ((size_t)v<<11))
    // 4 neurons per round, double-buffered table prefetch
#define NR_H(n0) { \
    ldcs_H(csa, TB((n0)+0), tid); \
    ldcs_H(csb, TB((n0)+1), tid); apply_neuron<3>(x, csa); \
    ldcs_H(csa, TB((n0)+2), tid); apply_neuron<2>(x, csb); \
    ldcs_H(csb, TB((n0)+3), tid); apply_neuron<1>(x, csa); \
    apply_neuron<0>(x, csb); }
#define NR_M(n0) { \
    ldcs_M(csa, TB((n0)+0), tid); \
    ldcs_M(csb, TB((n0)+1), tid); apply_neuron<3>(x, csa); \
    ldcs_M(csa, TB((n0)+2), tid); apply_neuron<2>(x, csb); \
    ldcs_M(csb, TB((n0)+3), tid); apply_neuron<1>(x, csa); \
    apply_neuron<0>(x, csb); }
#define NR_L(n0) { \
    ldcs_L(csa, TB((n0)+0), tid); \
    ldcs_L(csb, TB((n0)+1), tid); apply_neuron<3>(x, csa); \
    ldcs_L(csa, TB((n0)+2), tid); apply_neuron<2>(x, csb); \
    ldcs_L(csb, TB((n0)+3), tid); apply_neuron<1>(x, csa); \
    apply_neuron<0>(x, csb); }
#define RY4(stg, j0) { float sn, cn; \
    sincosf(w_u[(stg)*12 + (j0)+0], &sn, &cn); apply_ry<3>(x, cn, sn); \
    sincosf(w_u[(stg)*12 + (j0)+1], &sn, &cn); apply_ry<2>(x, cn, sn); \
    sincosf(w_u[(stg)*12 + (j0)+2], &sn, &cn); apply_ry<1>(x, cn, sn); \
    sincosf(w_u[(stg)*12 + (j0)+3], &sn, &cn); apply_ry<0>(x, cn, sn); }

    // R1: input neurons lanes 6..9 (tile bits 11..8), load straight from global
#pragma unroll
    for(int m=0;m<16;++m) x[m] = src[(m<<8)|tid];
    NR_H(0)
    str<0>(x, st, tid); __syncthreads();
    // R2
    ldr<1>(x, st, tid); NR_M(4); str<1>(x, st, tid); __syncthreads();
    // R3: input neurons bits 3..0, then Ry(st0) lanes 14..17
    ldr<2>(x, st, tid); NR_L(8); RY4(0, 8); str<2>(x, st, tid); __syncthreads();
    // R4
    ldr<1>(x, st, tid); RY4(0, 4); str<1>(x, st, tid); __syncthreads();
    // R5: Ry(st0) lanes 6..9 then neurons st0 bits 11..8
    ldr<0>(x, st, tid); RY4(0, 0); NR_H(12); str<0>(x, st, tid); __syncthreads();
    // R6
    ldr<1>(x, st, tid); NR_M(16); str<1>(x, st, tid); __syncthreads();
    // R7
    ldr<2>(x, st, tid); NR_L(20); RY4(1, 8); str<2>(x, st, tid); __syncthreads();
    // R8
    ldr<1>(x, st, tid); RY4(1, 4); str<1>(x, st, tid); __syncthreads();
    // R9
    ldr<0>(x, st, tid); RY4(1, 0); NR_H(24); str<0>(x, st, tid); __syncthreads();
    // R10
    ldr<1>(x, st, tid); NR_M(28); str<1>(x, st, tid); __syncthreads();
    // R11
    ldr<2>(x, st, tid); NR_L(32); RY4(2, 8); str<2>(x, st, tid); __syncthreads();
    // R12
    ldr<1>(x, st, tid); RY4(2, 4); str<1>(x, st, tid); __syncthreads();
    // R13
    ldr<0>(x, st, tid); RY4(2, 0); NR_H(36); str<0>(x, st, tid); __syncthreads();
    // R14
    ldr<1>(x, st, tid); NR_M(40); str<1>(x, st, tid); __syncthreads();
    // R15: neurons st2 bits 3..0; bounce through shared for coalesced store
    ldr<2>(x, st, tid); NR_L(44); str<2>(x, st, tid); __syncthreads();
#pragma unroll
    for(int k=0;k<16;++k){ int t = tid + (k<<8); dst[t] = st[sw(t)]; }

#undef TB
#undef NR_H
#undef NR_M
#undef NR_L
#undef RY4
}

// ---------------------------------------------------------------------------
__global__ void __launch_bounds__(256) k_pass2(
    u64* __restrict__ psi, float* __restrict__ probs)
{
    __shared__ u64 st[4096];
    __shared__ float sp[64];
    int tid = threadIdx.x;
    int b  = blockIdx.x >> 6;
    int m6 = blockIdx.x & 63;
    u64* base = psi + ((size_t)b<<18);
    if (tid < 64) sp[tid] = 0.0f;

    u64 x[16];
    float2 cs[8];

    // R1: H set (tile bits 11..8 in regs); tile t[11:6]=lanes0..5, t[5:0]=lanes12..17
    int t76 = tid >> 6, lo6 = tid & 63;
#pragma unroll
    for(int m=0;m<16;++m){
        int t = (m<<8)|tid;
        x[m] = base[((size_t)(t>>6)<<12) | (m6<<6) | (t&63)];
    }
#define NG2_H(j, K) { const float2* tb = g_tbl + ((size_t)(48+(j))<<TBL_BITS); \
    _Pragma("unroll") for(int mo=0;mo<8;++mo) \
        cs[mo] = __ldg(tb + (((mo<<2)|t76)<<12) + (m6<<6) + lo6); \
    apply_neuron<K>(x, cs); }
    NG2_H(0,3) NG2_H(1,2) NG2_H(2,1) NG2_H(3,0)
#undef NG2_H
    str<0>(x, st, tid); __syncthreads();

    // R2: M set (tile bits 7..4 in regs); neurons j=4 (bit7,K=3), j=5 (bit6,K=2)
    ldr<1>(x, st, tid);
    int hi = tid>>4, lo = tid&15;
    {
        const float2* tb = g_tbl + ((size_t)52<<TBL_BITS);
#pragma unroll
        for(int mo=0;mo<8;++mo)
            cs[mo] = __ldg(tb + ((((hi<<1)|(mo>>2))<<12) + (m6<<6) + ((mo&3)<<4) + lo));
        apply_neuron<3>(x, cs);
    }
    {
        const float2* tb = g_tbl + ((size_t)53<<TBL_BITS);
#pragma unroll
        for(int mo=0;mo<8;++mo)
            cs[mo] = __ldg(tb + ((((hi<<1)|(mo>>2))<<12) + (m6<<6) + ((mo&3)<<4) + lo));
        apply_neuron<2>(x, cs);
    }
    // store to global + probs marginal (prob index p = t[11:6] = (hi<<2)|(m>>2))
    float part[4] = {0.f, 0.f, 0.f, 0.f};
#pragma unroll
    for(int m=0;m<16;++m){
        int t = (hi<<8)|(m<<4)|lo;
        base[((size_t)(t>>6)<<12) | (m6<<6) | (t&63)] = x[m];
        float xl, xh;
        asm("mov.b64 {%0,%1},%2;" : "=f"(xl), "=f"(xh) : "l"(x[m]));
        part[m>>2] += fmaf(xl, xl, xh*xh);
    }
#pragma unroll
    for(int g=0; g<4; ++g) atomicAdd(&sp[(hi<<2)|g], part[g]);
    __syncthreads();
    if (tid < 64) atomicAdd(&probs[b*64 + tid], sp[tid]);
}

// ---------------------------------------------------------------------------
extern "C" void kernel_launch(void* const* d_in, const int* in_sizes, int n_in,
                              void* d_out, int out_size)
{
    (void)in_sizes; (void)n_in; (void)out_size;
    const float* w_in1  = (const float*)d_in[1];
    const float* w_in2  = (const float*)d_in[2];
    const float* w_u    = (const float*)d_in[3];
    const float* w_k1   = (const float*)d_in[4];
    const float* w_k2   = (const float*)d_in[5];
    const float* w_out1 = (const float*)d_in[6];
    const float* w_out2 = (const float*)d_in[7];
    const int*   inputs = (const int*)d_in[8];

    float* probs = (float*)d_out;                 // [32, 64]
    u64*   psi   = (u64*)(probs + 32 * 64);       // [32, 2^18] float2

    cudaMemsetAsync(probs, 0, 32 * 64 * sizeof(float));
    k_tables<<<54 * 256, 256>>>(w_in1, w_in2, w_k1, w_k2, w_out1, w_out2);
    k_pass1 <<<32 * 64, 256>>>((const u64*)d_in[0], inputs, w_u, psi);
    k_pass2 <<<32 * 64, 256>>>(psi, probs);
}